// round 13
// baseline (speedup 1.0000x reference)
#include <cuda_runtime.h>
#include <cuda_bf16.h>
#include <math.h>
#include <stdint.h>

#define NTOK   2048
#define DIM    1024
#define NHEADS 16
#define DHEAD  64
#define QKV_LD 3072

// ---------------- scratch (no allocations allowed) ----------------
__device__ float g_qkv [NTOK * QKV_LD];          // only k-columns used (fp32)
__device__ __nv_bfloat16 g_xn_hi[NTOK * DIM];
__device__ __nv_bfloat16 g_xn_lo[NTOK * DIM];
__device__ __nv_bfloat16 g_wqkv_hi[DIM * QKV_LD];
__device__ __nv_bfloat16 g_wqkv_lo[DIM * QKV_LD];
__device__ __nv_bfloat16 g_wo_hi[DIM * DIM];
__device__ __nv_bfloat16 g_wo_lo[DIM * DIM];
__device__ __nv_bfloat16 g_q_hi [NTOK * DIM];
__device__ __nv_bfloat16 g_q_lo [NTOK * DIM];
__device__ __nv_bfloat16 g_kt_hi[NHEADS * DHEAD * NTOK];  // [h][e][n]
__device__ __nv_bfloat16 g_kt_lo[NHEADS * DHEAD * NTOK];
__device__ __nv_bfloat16 g_v_hi [NTOK * DIM];
__device__ __nv_bfloat16 g_v_lo [NTOK * DIM];
__device__ __nv_bfloat16 g_ao_hi[NTOK * DIM];
__device__ __nv_bfloat16 g_ao_lo[NTOK * DIM];

static __device__ __forceinline__ uint32_t s2u(const void* p) {
    return (uint32_t)__cvta_generic_to_shared(p);
}

#define LDSM4(R, addr) \
    asm volatile("ldmatrix.sync.aligned.m8n8.x4.shared.b16 {%0,%1,%2,%3},[%4];" \
        : "=r"((R)[0]), "=r"((R)[1]), "=r"((R)[2]), "=r"((R)[3]) : "r"(addr))
#define LDSM4T(R, addr) \
    asm volatile("ldmatrix.sync.aligned.m8n8.x4.trans.shared.b16 {%0,%1,%2,%3},[%4];" \
        : "=r"((R)[0]), "=r"((R)[1]), "=r"((R)[2]), "=r"((R)[3]) : "r"(addr))
#define MMA_BF16(D, A, B) \
    asm volatile("mma.sync.aligned.m16n8k16.row.col.f32.bf16.bf16.f32 " \
        "{%0,%1,%2,%3},{%4,%5,%6,%7},{%8,%9},{%0,%1,%2,%3};" \
        : "+f"((D)[0]), "+f"((D)[1]), "+f"((D)[2]), "+f"((D)[3]) \
        : "r"((A)[0]), "r"((A)[1]), "r"((A)[2]), "r"((A)[3]), "r"((B)[0]), "r"((B)[1]))
#define CP16(dst, src) \
    asm volatile("cp.async.ca.shared.global [%0],[%1],16;" :: "r"(dst), "l"(src))
#define CPCOMMIT() asm volatile("cp.async.commit_group;")
#define CPWAIT(n)  asm volatile("cp.async.wait_group %0;" :: "n"(n))

static __device__ __forceinline__ void split2(float x, float y,
                                              uint32_t& hi, uint32_t& lo) {
    float2 f; f.x = x; f.y = y;
    __nv_bfloat162 h = __float22bfloat162_rn(f);
    float2 hf = __bfloat1622float2(h);
    float2 r; r.x = x - hf.x; r.y = y - hf.y;
    __nv_bfloat162 l = __float22bfloat162_rn(r);
    hi = *(uint32_t*)&h; lo = *(uint32_t*)&l;
}

// ---------------- RoPE pair helper ----------------
__device__ __forceinline__ void rope_pair(int row, int c, const float2 xv,
                                          float scale, float& y0, float& y1) {
    const int dd = c & 63;
    const int f0 = (dd < 32) ? dd : dd - 32;
    const int f1 = (dd + 1 < 32) ? dd + 1 : dd - 31;
    const float th0 = powf(10000.f, -(float)f0 * (1.f / 32.f));
    const float th1 = powf(10000.f, -(float)f1 * (1.f / 32.f));
    const float pos = (float)row;
    const float a0 = pos * th0;
    const float a1 = pos * th1;
    y0 = (xv.x * cosf(a0) - xv.y * sinf(a0)) * scale;
    y1 = (xv.y * cosf(a1) + xv.x * sinf(a1)) * scale;
}

// ---------------- LayerNorm -> split bf16 ----------------
__global__ void ln_kernel(const float* __restrict__ x,
                          const float* __restrict__ gamma,
                          __nv_bfloat16* __restrict__ xhi,
                          __nv_bfloat16* __restrict__ xlo) {
    __shared__ float red[16];
    const int row = blockIdx.x;
    const float2* xr = reinterpret_cast<const float2*>(x + (long)row * DIM);
    float2 v[2];
    float s = 0.f, ss = 0.f;
#pragma unroll
    for (int i = 0; i < 2; i++) {
        v[i] = xr[threadIdx.x + i * 256];
        s += v[i].x + v[i].y;
        ss += v[i].x * v[i].x + v[i].y * v[i].y;
    }
#pragma unroll
    for (int o = 16; o > 0; o >>= 1) {
        s  += __shfl_xor_sync(0xffffffffu, s,  o);
        ss += __shfl_xor_sync(0xffffffffu, ss, o);
    }
    if ((threadIdx.x & 31) == 0) {
        red[threadIdx.x >> 5]       = s;
        red[8 + (threadIdx.x >> 5)] = ss;
    }
    __syncthreads();
    s = red[0]; ss = red[8];
#pragma unroll
    for (int i = 1; i < 8; i++) { s += red[i]; ss += red[8 + i]; }
    const float mu  = s * (1.f / DIM);
    const float var = ss * (1.f / DIM) - mu * mu;
    const float inv = rsqrtf(var + 1e-5f);
    const float2* g2 = reinterpret_cast<const float2*>(gamma);
#pragma unroll
    for (int i = 0; i < 2; i++) {
        const int p = threadIdx.x + i * 256;
        const float2 gg = g2[p];
        const float y0 = (v[i].x - mu) * inv * gg.x;
        const float y1 = (v[i].y - mu) * inv * gg.y;
        uint32_t h, l;
        split2(y0, y1, h, l);
        *(uint32_t*)&xhi[(long)row * DIM + 2 * p] = h;
        *(uint32_t*)&xlo[(long)row * DIM + 2 * p] = l;
    }
}

// ---------------- weight split: [Wq | Wkv] -> combined [1024][3072] hi/lo ----------------
__global__ void wsplit_qkv(const float* __restrict__ Wq,
                           const float* __restrict__ Wkv,
                           __nv_bfloat16* __restrict__ hi,
                           __nv_bfloat16* __restrict__ lo) {
    const int r = blockIdx.y;
    const int c = (blockIdx.x * blockDim.x + threadIdx.x) * 2;
    float2 v;
    if (c < DIM) v = *reinterpret_cast<const float2*>(Wq + (long)r * DIM + c);
    else         v = *reinterpret_cast<const float2*>(Wkv + (long)r * 2 * DIM + (c - DIM));
    uint32_t h, l;
    split2(v.x, v.y, h, l);
    *(uint32_t*)&hi[(long)r * QKV_LD + c] = h;
    *(uint32_t*)&lo[(long)r * QKV_LD + c] = l;
}

// ---------------- generic split: 1024 cols fp32 -> bf16 hi/lo ----------------
__global__ void split_kernel(const float* __restrict__ src, int lds,
                             __nv_bfloat16* __restrict__ hi,
                             __nv_bfloat16* __restrict__ lo, int ldd) {
    const int idx = blockIdx.x * blockDim.x + threadIdx.x;
    const int row = idx >> 9;
    const int c   = (idx & 511) * 2;
    const float2 xv = *reinterpret_cast<const float2*>(src + (long)row * lds + c);
    uint32_t h, l;
    split2(xv.x, xv.y, h, l);
    *(uint32_t*)&hi[(long)row * ldd + c] = h;
    *(uint32_t*)&lo[(long)row * ldd + c] = l;
}

// ---------------- pure-bf16 3-product GEMM, 2-stage cp.async ----------------
// MODE 0: plain fp32 C.  MODE 1: QKV epilogue (q->rope+split, k->fp32, v->split).
#define GA_ELE 5120   // 128*40
#define GB_ELE 4352   // 32*136
#define GSTAGE (2 * GA_ELE + 2 * GB_ELE)

template <int MODE>
__global__ __launch_bounds__(256)
void gemm_bf16p(const __nv_bfloat16* __restrict__ Ahi,
                const __nv_bfloat16* __restrict__ Alo,
                const __nv_bfloat16* __restrict__ Bhi,
                const __nv_bfloat16* __restrict__ Blo,
                float* __restrict__ C,
                int K, int lda, int ldb, int ldc,
                __nv_bfloat16* __restrict__ qhi,
                __nv_bfloat16* __restrict__ qlo,
                __nv_bfloat16* __restrict__ vhi,
                __nv_bfloat16* __restrict__ vlo) {
    extern __shared__ __align__(16) __nv_bfloat16 gsm[];

    const int tid  = threadIdx.x;
    const int lane = tid & 31;
    const int wid  = tid >> 5;
    const int wm   = wid >> 2;
    const int wn   = wid & 3;
    const int brow = blockIdx.y * 128;
    const int bcol = blockIdx.x * 128;

    float d[4][4][4];
#pragma unroll
    for (int i = 0; i < 4; i++)
#pragma unroll
        for (int j = 0; j < 4; j++)
#pragma unroll
            for (int r = 0; r < 4; r++) d[i][j][r] = 0.f;

    const int niter = K / 32;

    auto load_stage = [&](int kt, int st) {
        __nv_bfloat16* As_hi = gsm + st * GSTAGE;
        __nv_bfloat16* As_lo = As_hi + GA_ELE;
        __nv_bfloat16* Bs_hi = As_lo + GA_ELE;
        __nv_bfloat16* Bs_lo = Bs_hi + GB_ELE;
        const int k0 = kt * 32;
#pragma unroll
        for (int t = 0; t < 2; t++) {
            const int p  = tid + t * 256;
            const int ar = p >> 2, ac = (p & 3) * 8;
            CP16(s2u(As_hi + ar * 40 + ac), Ahi + (long)(brow + ar) * lda + k0 + ac);
            CP16(s2u(As_lo + ar * 40 + ac), Alo + (long)(brow + ar) * lda + k0 + ac);
            const int br = p >> 4, bc = (p & 15) * 8;
            CP16(s2u(Bs_hi + br * 136 + bc), Bhi + (long)(k0 + br) * ldb + bcol + bc);
            CP16(s2u(Bs_lo + br * 136 + bc), Blo + (long)(k0 + br) * ldb + bcol + bc);
        }
    };

    load_stage(0, 0);
    CPCOMMIT();

    for (int kt = 0; kt < niter; kt++) {
        if (kt + 1 < niter) {
            load_stage(kt + 1, (kt + 1) & 1);
            CPCOMMIT();
            CPWAIT(1);
        } else {
            CPWAIT(0);
        }
        __syncthreads();

        const __nv_bfloat16* As_hi = gsm + (kt & 1) * GSTAGE;
        const __nv_bfloat16* As_lo = As_hi + GA_ELE;
        const __nv_bfloat16* Bs_hi = As_lo + GA_ELE;
        const __nv_bfloat16* Bs_lo = Bs_hi + GB_ELE;
        const int g  = lane >> 3;
        const int ri = lane & 7;

#pragma unroll
        for (int kk = 0; kk < 32; kk += 16) {
            uint32_t a_hi[4][4], a_lo[4][4], b_hi[2][4], b_lo[2][4];
#pragma unroll
            for (int mi = 0; mi < 4; mi++) {
                const int row   = wm * 64 + mi * 16 + (g & 1) * 8 + ri;
                const int chunk = (kk >> 3) + (g >> 1);
                LDSM4(a_hi[mi], s2u(As_hi) + row * 80 + chunk * 16);
                LDSM4(a_lo[mi], s2u(As_lo) + row * 80 + chunk * 16);
            }
#pragma unroll
            for (int nj2 = 0; nj2 < 2; nj2++) {
                const int krow = kk + (g & 1) * 8 + ri;
                const int col  = wn * 32 + nj2 * 16 + (g >> 1) * 8;
                LDSM4T(b_hi[nj2], s2u(Bs_hi) + krow * 272 + col * 2);
                LDSM4T(b_lo[nj2], s2u(Bs_lo) + krow * 272 + col * 2);
            }
#pragma unroll
            for (int mi = 0; mi < 4; mi++)
#pragma unroll
                for (int nj = 0; nj < 4; nj++) {
                    const int nj2 = nj >> 1, u = (nj & 1) * 2;
                    MMA_BF16(d[mi][nj], a_hi[mi], b_hi[nj2] + u);
                    MMA_BF16(d[mi][nj], a_hi[mi], b_lo[nj2] + u);
                    MMA_BF16(d[mi][nj], a_lo[mi], b_hi[nj2] + u);
                }
        }
        __syncthreads();
    }

    // epilogue
#pragma unroll
    for (int mi = 0; mi < 4; mi++)
#pragma unroll
        for (int nj = 0; nj < 4; nj++) {
            const int r  = brow + wm * 64 + mi * 16 + (lane >> 2);
            const int cc = bcol + wn * 32 + nj * 8 + (lane & 3) * 2;
            float2 t0, t1;
            t0.x = d[mi][nj][0]; t0.y = d[mi][nj][1];
            t1.x = d[mi][nj][2]; t1.y = d[mi][nj][3];
            if (MODE == 0) {
                *reinterpret_cast<float2*>(C + (long)r * ldc + cc)       = t0;
                *reinterpret_cast<float2*>(C + (long)(r + 8) * ldc + cc) = t1;
            } else {
                if (cc < DIM) {               // Q: rope + scale + split
                    float y0, y1;
                    uint32_t h, l;
                    rope_pair(r, cc, t0, 0.125f, y0, y1);
                    split2(y0, y1, h, l);
                    *(uint32_t*)&qhi[(long)r * DIM + cc] = h;
                    *(uint32_t*)&qlo[(long)r * DIM + cc] = l;
                    rope_pair(r + 8, cc, t1, 0.125f, y0, y1);
                    split2(y0, y1, h, l);
                    *(uint32_t*)&qhi[(long)(r + 8) * DIM + cc] = h;
                    *(uint32_t*)&qlo[(long)(r + 8) * DIM + cc] = l;
                } else if (cc < 2 * DIM) {    // K: fp32 for bilinear
                    *reinterpret_cast<float2*>(C + (long)r * ldc + cc)       = t0;
                    *reinterpret_cast<float2*>(C + (long)(r + 8) * ldc + cc) = t1;
                } else {                      // V: split
                    const int vc = cc - 2 * DIM;
                    uint32_t h, l;
                    split2(t0.x, t0.y, h, l);
                    *(uint32_t*)&vhi[(long)r * DIM + vc] = h;
                    *(uint32_t*)&vlo[(long)r * DIM + vc] = l;
                    split2(t1.x, t1.y, h, l);
                    *(uint32_t*)&vhi[(long)(r + 8) * DIM + vc] = h;
                    *(uint32_t*)&vlo[(long)(r + 8) * DIM + vc] = l;
                }
            }
        }
}

// ---------------- bilinear K transform with fused RoPE, split output ----------------
__global__ void bilinear_kernel(const float* __restrict__ k, int ldk,
                                const float* __restrict__ Wb,
                                __nv_bfloat16* __restrict__ kthi,
                                __nv_bfloat16* __restrict__ ktlo) {
    const int h = blockIdx.y;
    const int rowbase = blockIdx.x * 64;
    __shared__ float Wbs[64][64];
    __shared__ float ks[64][65];
    for (int p = threadIdx.x; p < 64 * 64; p += 256)
        Wbs[p / 64][p % 64] = Wb[h * 4096 + p];
    for (int p = threadIdx.x; p < 64 * 32; p += 256) {
        const int r  = p >> 5;
        const int dd = (p & 31) * 2;
        const float2 kv = *reinterpret_cast<const float2*>(
            k + (long)(rowbase + r) * ldk + h * 64 + dd);
        float y0, y1;
        rope_pair(rowbase + r, dd, kv, 1.0f, y0, y1);
        ks[r][dd]     = y0;
        ks[r][dd + 1] = y1;
    }
    __syncthreads();
    for (int p = threadIdx.x; p < 64 * 64; p += 256) {
        const int e = p / 64, r = p % 64;
        float s = 0.f;
#pragma unroll
        for (int dd = 0; dd < 64; dd++) s = fmaf(ks[r][dd], Wbs[dd][e], s);
        const long o = ((long)h * 64 + e) * NTOK + rowbase + r;
        const __nv_bfloat16 bh = __float2bfloat16_rn(s);
        kthi[o] = bh;
        ktlo[o] = __float2bfloat16_rn(s - __bfloat162float(bh));
    }
}

// ---------------- tensor-core flash attention v2 ----------------
// Q hi/lo in dedicated smem (Q frags reloaded per iter), K/V double-buffered,
// P frags built inline per kc. Targets 2 CTAs/SM.
#define FSTR    72
#define FQ_ELE  (128 * FSTR)   // 9216
#define FKV_ELE (64 * FSTR)    // 4608
#define FLASH_SMEM ((2 * FQ_ELE + 8 * FKV_ELE) * (int)sizeof(__nv_bfloat16))  // 110592

__global__ __launch_bounds__(256, 2)
void flash_mma(const __nv_bfloat16* __restrict__ qhi,
               const __nv_bfloat16* __restrict__ qlo,
               const __nv_bfloat16* __restrict__ kthi,
               const __nv_bfloat16* __restrict__ ktlo,
               const __nv_bfloat16* __restrict__ vhi,
               const __nv_bfloat16* __restrict__ vlo,
               __nv_bfloat16* __restrict__ aohi,
               __nv_bfloat16* __restrict__ aolo) {
    extern __shared__ __align__(16) __nv_bfloat16 fsm[];
    __nv_bfloat16* QH = fsm;
    __nv_bfloat16* QL = fsm + FQ_ELE;
    __nv_bfloat16* KH = fsm + 2 * FQ_ELE;
    __nv_bfloat16* KL = KH + 2 * FKV_ELE;
    __nv_bfloat16* VH = KH + 4 * FKV_ELE;
    __nv_bfloat16* VL = KH + 6 * FKV_ELE;

    const int h     = blockIdx.y;
    const int qbase = blockIdx.x * 128;
    const int tid   = threadIdx.x;
    const int lane  = tid & 31;
    const int w     = tid >> 5;
    const int g     = lane >> 3;
    const int ri    = lane & 7;

    auto load_kv = [&](int j0, int st) {
        __nv_bfloat16* kh = KH + st * FKV_ELE;
        __nv_bfloat16* kl = KL + st * FKV_ELE;
        __nv_bfloat16* vh = VH + st * FKV_ELE;
        __nv_bfloat16* vl = VL + st * FKV_ELE;
#pragma unroll
        for (int t = 0; t < 2; t++) {
            const int p = tid + t * 256;
            const int e = p >> 3, jc = (p & 7) * 8;
            CP16(s2u(kh + e * FSTR + jc), kthi + ((long)h * 64 + e) * NTOK + j0 + jc);
            CP16(s2u(kl + e * FSTR + jc), ktlo + ((long)h * 64 + e) * NTOK + j0 + jc);
            CP16(s2u(vh + e * FSTR + jc), vhi + (long)(j0 + e) * DIM + h * 64 + jc);
            CP16(s2u(vl + e * FSTR + jc), vlo + (long)(j0 + e) * DIM + h * 64 + jc);
        }
    };

    // stage Q (persistent) + first KV tile, one commit group
#pragma unroll
    for (int t = 0; t < 4; t++) {
        const int p = tid + t * 256;
        const int i = p >> 3, ec = (p & 7) * 8;
        const long go = (long)(qbase + i) * DIM + h * 64 + ec;
        CP16(s2u(QH + i * FSTR + ec), qhi + go);
        CP16(s2u(QL + i * FSTR + ec), qlo + go);
    }
    load_kv(0, 0);
    CPCOMMIT();

    float o[8][4];
    float m0 = -3.4e38f, m1 = -3.4e38f, l0 = 0.f, l1 = 0.f;
#pragma unroll
    for (int t = 0; t < 8; t++)
#pragma unroll
        for (int r = 0; r < 4; r++) o[t][r] = 0.f;

    const int qrow = w * 16 + (g & 1) * 8 + ri;

    for (int it = 0; it < NTOK / 64; it++) {
        if (it + 1 < NTOK / 64) {
            load_kv((it + 1) * 64, (it + 1) & 1);
            CPCOMMIT();
            CPWAIT(1);
        } else {
            CPWAIT(0);
        }
        __syncthreads();

        const __nv_bfloat16* kh = KH + (it & 1) * FKV_ELE;
        const __nv_bfloat16* kl = KL + (it & 1) * FKV_ELE;
        const __nv_bfloat16* vh = VH + (it & 1) * FKV_ELE;
        const __nv_bfloat16* vl = VL + (it & 1) * FKV_ELE;

        // ---- S = Q @ Kt (3-product); Q frags reloaded from persistent smem ----
        float s[8][4];
#pragma unroll
        for (int t = 0; t < 8; t++)
#pragma unroll
            for (int r = 0; r < 4; r++) s[t][r] = 0.f;
#pragma unroll
        for (int kc = 0; kc < 4; kc++) {
            uint32_t aqh[4], aql[4];
            const int qcolb = (kc * 16 + (g >> 1) * 8) * 2;
            LDSM4(aqh, s2u(QH) + qrow * (FSTR * 2) + qcolb);
            LDSM4(aql, s2u(QL) + qrow * (FSTR * 2) + qcolb);
            const int krow = kc * 16 + (g & 1) * 8 + ri;
#pragma unroll
            for (int ng = 0; ng < 4; ng++) {
                uint32_t bh[4], bl[4];
                const int colb = (ng * 16 + (g >> 1) * 8) * 2;
                LDSM4T(bh, s2u(kh) + krow * (FSTR * 2) + colb);
                LDSM4T(bl, s2u(kl) + krow * (FSTR * 2) + colb);
                MMA_BF16(s[2 * ng],     aqh, bh);
                MMA_BF16(s[2 * ng],     aqh, bl);
                MMA_BF16(s[2 * ng],     aql, bh);
                MMA_BF16(s[2 * ng + 1], aqh, bh + 2);
                MMA_BF16(s[2 * ng + 1], aqh, bl + 2);
                MMA_BF16(s[2 * ng + 1], aql, bh + 2);
            }
        }

        // ---- online softmax ----
        float mx0 = -3.4e38f, mx1 = -3.4e38f;
#pragma unroll
        for (int t = 0; t < 8; t++) {
            mx0 = fmaxf(mx0, fmaxf(s[t][0], s[t][1]));
            mx1 = fmaxf(mx1, fmaxf(s[t][2], s[t][3]));
        }
        mx0 = fmaxf(mx0, __shfl_xor_sync(0xffffffffu, mx0, 1));
        mx0 = fmaxf(mx0, __shfl_xor_sync(0xffffffffu, mx0, 2));
        mx1 = fmaxf(mx1, __shfl_xor_sync(0xffffffffu, mx1, 1));
        mx1 = fmaxf(mx1, __shfl_xor_sync(0xffffffffu, mx1, 2));
        const float mn0 = fmaxf(m0, mx0);
        const float mn1 = fmaxf(m1, mx1);
        const float c0  = __expf(m0 - mn0);
        const float c1  = __expf(m1 - mn1);
        m0 = mn0; m1 = mn1;
        float rs0 = 0.f, rs1 = 0.f;
#pragma unroll
        for (int t = 0; t < 8; t++) {
            s[t][0] = __expf(s[t][0] - mn0);
            s[t][1] = __expf(s[t][1] - mn0);
            s[t][2] = __expf(s[t][2] - mn1);
            s[t][3] = __expf(s[t][3] - mn1);
            rs0 += s[t][0] + s[t][1];
            rs1 += s[t][2] + s[t][3];
        }
        rs0 += __shfl_xor_sync(0xffffffffu, rs0, 1);
        rs0 += __shfl_xor_sync(0xffffffffu, rs0, 2);
        rs1 += __shfl_xor_sync(0xffffffffu, rs1, 1);
        rs1 += __shfl_xor_sync(0xffffffffu, rs1, 2);
        l0 = l0 * c0 + rs0;
        l1 = l1 * c1 + rs1;
#pragma unroll
        for (int t = 0; t < 8; t++) {
            o[t][0] *= c0; o[t][1] *= c0;
            o[t][2] *= c1; o[t][3] *= c1;
        }

        // ---- O += P @ V (3-product); P frags built inline per kc ----
#pragma unroll
        for (int kc = 0; kc < 4; kc++) {
            uint32_t aph[4], apl[4];
            split2(s[2 * kc][0],     s[2 * kc][1],     aph[0], apl[0]);
            split2(s[2 * kc][2],     s[2 * kc][3],     aph[1], apl[1]);
            split2(s[2 * kc + 1][0], s[2 * kc + 1][1], aph[2], apl[2]);
            split2(s[2 * kc + 1][2], s[2 * kc + 1][3], aph[3], apl[3]);
            const int krow = kc * 16 + (g & 1) * 8 + ri;
#pragma unroll
            for (int ng = 0; ng < 4; ng++) {
                uint32_t bh[4], bl[4];
                const int colb = (ng * 16 + (g >> 1) * 8) * 2;
                LDSM4T(bh, s2u(vh) + krow * (FSTR * 2) + colb);
                LDSM4T(bl, s2u(vl) + krow * (FSTR * 2) + colb);
                MMA_BF16(o[2 * ng],     aph, bh);
                MMA_BF16(o[2 * ng],     aph, bl);
                MMA_BF16(o[2 * ng],     apl, bh);
                MMA_BF16(o[2 * ng + 1], aph, bh + 2);
                MMA_BF16(o[2 * ng + 1], aph, bl + 2);
                MMA_BF16(o[2 * ng + 1], apl, bh + 2);
            }
        }
        __syncthreads();
    }

    // ---- epilogue: normalize + split-store for Wo GEMM ----
    const float i0 = 1.f / l0;
    const float i1 = 1.f / l1;
    const int r  = qbase + w * 16 + (lane >> 2);
#pragma unroll
    for (int t = 0; t < 8; t++) {
        const int cc = h * 64 + t * 8 + (lane & 3) * 2;
        uint32_t h0, l0u, h1, l1u;
        split2(o[t][0] * i0, o[t][1] * i0, h0, l0u);
        split2(o[t][2] * i1, o[t][3] * i1, h1, l1u);
        *(uint32_t*)&aohi[(long)r * DIM + cc]       = h0;
        *(uint32_t*)&aolo[(long)r * DIM + cc]       = l0u;
        *(uint32_t*)&aohi[(long)(r + 8) * DIM + cc] = h1;
        *(uint32_t*)&aolo[(long)(r + 8) * DIM + cc] = l1u;
    }
}

// ---------------- launch ----------------
extern "C" void kernel_launch(void* const* d_in, const int* in_sizes, int n_in,
                              void* d_out, int out_size) {
    const float* x     = (const float*)d_in[0];
    const float* gamma = (const float*)d_in[1];
    const float* Wq    = (const float*)d_in[2];
    const float* Wkv   = (const float*)d_in[3];
    const float* Wb    = (const float*)d_in[4];
    const float* Wo    = (const float*)d_in[5];
    float* out = (float*)d_out;

    float* qkv;
    __nv_bfloat16 *xn_hi, *xn_lo, *wqkv_hi, *wqkv_lo, *wo_hi, *wo_lo;
    __nv_bfloat16 *q_hi, *q_lo, *kt_hi, *kt_lo, *v_hi, *v_lo, *ao_hi, *ao_lo;
    cudaGetSymbolAddress((void**)&qkv,     g_qkv);
    cudaGetSymbolAddress((void**)&xn_hi,   g_xn_hi);
    cudaGetSymbolAddress((void**)&xn_lo,   g_xn_lo);
    cudaGetSymbolAddress((void**)&wqkv_hi, g_wqkv_hi);
    cudaGetSymbolAddress((void**)&wqkv_lo, g_wqkv_lo);
    cudaGetSymbolAddress((void**)&wo_hi,   g_wo_hi);
    cudaGetSymbolAddress((void**)&wo_lo,   g_wo_lo);
    cudaGetSymbolAddress((void**)&q_hi,    g_q_hi);
    cudaGetSymbolAddress((void**)&q_lo,    g_q_lo);
    cudaGetSymbolAddress((void**)&kt_hi,   g_kt_hi);
    cudaGetSymbolAddress((void**)&kt_lo,   g_kt_lo);
    cudaGetSymbolAddress((void**)&v_hi,    g_v_hi);
    cudaGetSymbolAddress((void**)&v_lo,    g_v_lo);
    cudaGetSymbolAddress((void**)&ao_hi,   g_ao_hi);
    cudaGetSymbolAddress((void**)&ao_lo,   g_ao_lo);

    float* k = qkv + DIM;

    const int gemm_smem = GSTAGE * 2 * (int)sizeof(__nv_bfloat16);   // 75776
    cudaFuncSetAttribute(gemm_bf16p<0>,
                         cudaFuncAttributeMaxDynamicSharedMemorySize, gemm_smem);
    cudaFuncSetAttribute(gemm_bf16p<1>,
                         cudaFuncAttributeMaxDynamicSharedMemorySize, gemm_smem);
    cudaFuncSetAttribute(flash_mma,
                         cudaFuncAttributeMaxDynamicSharedMemorySize, FLASH_SMEM);

    // 1. LayerNorm -> split bf16
    ln_kernel<<<NTOK, 256>>>(x, gamma, xn_hi, xn_lo);

    // 1b. weight splits (independent)
    wsplit_qkv<<<dim3(QKV_LD / 512, DIM), 256>>>(Wq, Wkv, wqkv_hi, wqkv_lo);
    split_kernel<<<DIM * 512 / 256, 256>>>(Wo, DIM, wo_hi, wo_lo, DIM);

    // 2. qkv = xn @ [Wq | Wkv] with fused epilogue (q rope+split, k fp32, v split)
    gemm_bf16p<1><<<dim3(QKV_LD / 128, NTOK / 128), 256, gemm_smem>>>(
        xn_hi, xn_lo, wqkv_hi, wqkv_lo, qkv, DIM, DIM, QKV_LD, QKV_LD,
        q_hi, q_lo, v_hi, v_lo);

    // 3. bilinear K transform (RoPE fused on load) -> kt hi/lo [h][e][n]
    bilinear_kernel<<<dim3(NTOK / 64, NHEADS), 256>>>(k, QKV_LD, Wb, kt_hi, kt_lo);

    // 4. flash attention -> ao split bf16
    flash_mma<<<dim3(NTOK / 128, NHEADS), 256, FLASH_SMEM>>>(
        q_hi, q_lo, kt_hi, kt_lo, v_hi, v_lo, ao_hi, ao_lo);

    // 5. out = ao @ Wo
    gemm_bf16p<0><<<dim3(DIM / 128, NTOK / 128), 256, gemm_smem>>>(
        ao_hi, ao_lo, wo_hi, wo_lo, out, DIM, DIM, DIM, DIM,
        nullptr, nullptr, nullptr, nullptr);
}

// round 14
// speedup vs baseline: 1.0837x; 1.0837x over previous
#include <cuda_runtime.h>
#include <cuda_bf16.h>
#include <math.h>
#include <stdint.h>

#define NTOK   2048
#define DIM    1024
#define NHEADS 16
#define DHEAD  64
#define QKV_LD 3072

// ---------------- scratch (no allocations allowed) ----------------
__device__ float g_qkv [NTOK * QKV_LD];          // only k-columns used (fp32)
__device__ float g_rc  [NTOK * 32];              // rope cos table [pos][j]
__device__ float g_rs  [NTOK * 32];              // rope sin table [pos][j]
__device__ __nv_bfloat16 g_xn_hi[NTOK * DIM];
__device__ __nv_bfloat16 g_xn_lo[NTOK * DIM];
__device__ __nv_bfloat16 g_wqkv_hi[DIM * QKV_LD];
__device__ __nv_bfloat16 g_wqkv_lo[DIM * QKV_LD];
__device__ __nv_bfloat16 g_wo_hi[DIM * DIM];
__device__ __nv_bfloat16 g_wo_lo[DIM * DIM];
__device__ __nv_bfloat16 g_q_hi [NTOK * DIM];
__device__ __nv_bfloat16 g_q_lo [NTOK * DIM];
__device__ __nv_bfloat16 g_kt_hi[NHEADS * DHEAD * NTOK];  // [h][e][n]
__device__ __nv_bfloat16 g_kt_lo[NHEADS * DHEAD * NTOK];
__device__ __nv_bfloat16 g_v_hi [NTOK * DIM];
__device__ __nv_bfloat16 g_v_lo [NTOK * DIM];
__device__ __nv_bfloat16 g_ao_hi[NTOK * DIM];
__device__ __nv_bfloat16 g_ao_lo[NTOK * DIM];

static __device__ __forceinline__ uint32_t s2u(const void* p) {
    return (uint32_t)__cvta_generic_to_shared(p);
}

#define LDSM4(R, addr) \
    asm volatile("ldmatrix.sync.aligned.m8n8.x4.shared.b16 {%0,%1,%2,%3},[%4];" \
        : "=r"((R)[0]), "=r"((R)[1]), "=r"((R)[2]), "=r"((R)[3]) : "r"(addr))
#define LDSM4T(R, addr) \
    asm volatile("ldmatrix.sync.aligned.m8n8.x4.trans.shared.b16 {%0,%1,%2,%3},[%4];" \
        : "=r"((R)[0]), "=r"((R)[1]), "=r"((R)[2]), "=r"((R)[3]) : "r"(addr))
#define MMA_BF16(D, A, B) \
    asm volatile("mma.sync.aligned.m16n8k16.row.col.f32.bf16.bf16.f32 " \
        "{%0,%1,%2,%3},{%4,%5,%6,%7},{%8,%9},{%0,%1,%2,%3};" \
        : "+f"((D)[0]), "+f"((D)[1]), "+f"((D)[2]), "+f"((D)[3]) \
        : "r"((A)[0]), "r"((A)[1]), "r"((A)[2]), "r"((A)[3]), "r"((B)[0]), "r"((B)[1]))
#define CP16(dst, src) \
    asm volatile("cp.async.ca.shared.global [%0],[%1],16;" :: "r"(dst), "l"(src))
#define CPCOMMIT() asm volatile("cp.async.commit_group;")
#define CPWAIT(n)  asm volatile("cp.async.wait_group %0;" :: "n"(n))

static __device__ __forceinline__ void split2(float x, float y,
                                              uint32_t& hi, uint32_t& lo) {
    float2 f; f.x = x; f.y = y;
    __nv_bfloat162 h = __float22bfloat162_rn(f);
    float2 hf = __bfloat1622float2(h);
    float2 r; r.x = x - hf.x; r.y = y - hf.y;
    __nv_bfloat162 l = __float22bfloat162_rn(r);
    hi = *(uint32_t*)&h; lo = *(uint32_t*)&l;
}

// ---------------- rope table generation (accurate cosf/sinf, one-off) ----------------
__global__ void rope_tab(float* __restrict__ rc, float* __restrict__ rs) {
    const int idx = blockIdx.x * blockDim.x + threadIdx.x;  // NTOK*32
    const int pos = idx >> 5;
    const int j   = idx & 31;
    const float th = powf(10000.f, -(float)j * (1.f / 32.f));
    const float a  = (float)pos * th;
    rc[idx] = cosf(a);
    rs[idx] = sinf(a);
}

// ---------------- table-based RoPE pair ----------------
__device__ __forceinline__ void rope_pair_tab(const float* __restrict__ rc,
                                              const float* __restrict__ rs,
                                              int row, int c, const float2 xv,
                                              float scale, float& y0, float& y1) {
    const int dd = c & 63;                       // even in [0,62]
    const int i0 = (dd < 32) ? dd : dd - 32;
    const int i1 = (dd + 1 < 32) ? dd + 1 : dd - 31;
    const float c0 = rc[row * 32 + i0], s0 = rs[row * 32 + i0];
    const float c1 = rc[row * 32 + i1], s1 = rs[row * 32 + i1];
    y0 = (xv.x * c0 - xv.y * s0) * scale;
    y1 = (xv.y * c1 + xv.x * s1) * scale;
}

// ---------------- LayerNorm -> split bf16 ----------------
__global__ void ln_kernel(const float* __restrict__ x,
                          const float* __restrict__ gamma,
                          __nv_bfloat16* __restrict__ xhi,
                          __nv_bfloat16* __restrict__ xlo) {
    __shared__ float red[16];
    const int row = blockIdx.x;
    const float2* xr = reinterpret_cast<const float2*>(x + (long)row * DIM);
    float2 v[2];
    float s = 0.f, ss = 0.f;
#pragma unroll
    for (int i = 0; i < 2; i++) {
        v[i] = xr[threadIdx.x + i * 256];
        s += v[i].x + v[i].y;
        ss += v[i].x * v[i].x + v[i].y * v[i].y;
    }
#pragma unroll
    for (int o = 16; o > 0; o >>= 1) {
        s  += __shfl_xor_sync(0xffffffffu, s,  o);
        ss += __shfl_xor_sync(0xffffffffu, ss, o);
    }
    if ((threadIdx.x & 31) == 0) {
        red[threadIdx.x >> 5]       = s;
        red[8 + (threadIdx.x >> 5)] = ss;
    }
    __syncthreads();
    s = red[0]; ss = red[8];
#pragma unroll
    for (int i = 1; i < 8; i++) { s += red[i]; ss += red[8 + i]; }
    const float mu  = s * (1.f / DIM);
    const float var = ss * (1.f / DIM) - mu * mu;
    const float inv = rsqrtf(var + 1e-5f);
    const float2* g2 = reinterpret_cast<const float2*>(gamma);
#pragma unroll
    for (int i = 0; i < 2; i++) {
        const int p = threadIdx.x + i * 256;
        const float2 gg = g2[p];
        const float y0 = (v[i].x - mu) * inv * gg.x;
        const float y1 = (v[i].y - mu) * inv * gg.y;
        uint32_t h, l;
        split2(y0, y1, h, l);
        *(uint32_t*)&xhi[(long)row * DIM + 2 * p] = h;
        *(uint32_t*)&xlo[(long)row * DIM + 2 * p] = l;
    }
}

// ---------------- weight split: [Wq | Wkv] -> combined [1024][3072] hi/lo ----------------
__global__ void wsplit_qkv(const float* __restrict__ Wq,
                           const float* __restrict__ Wkv,
                           __nv_bfloat16* __restrict__ hi,
                           __nv_bfloat16* __restrict__ lo) {
    const int r = blockIdx.y;
    const int c = (blockIdx.x * blockDim.x + threadIdx.x) * 2;
    float2 v;
    if (c < DIM) v = *reinterpret_cast<const float2*>(Wq + (long)r * DIM + c);
    else         v = *reinterpret_cast<const float2*>(Wkv + (long)r * 2 * DIM + (c - DIM));
    uint32_t h, l;
    split2(v.x, v.y, h, l);
    *(uint32_t*)&hi[(long)r * QKV_LD + c] = h;
    *(uint32_t*)&lo[(long)r * QKV_LD + c] = l;
}

// ---------------- generic split: 1024 cols fp32 -> bf16 hi/lo ----------------
__global__ void split_kernel(const float* __restrict__ src, int lds,
                             __nv_bfloat16* __restrict__ hi,
                             __nv_bfloat16* __restrict__ lo, int ldd) {
    const int idx = blockIdx.x * blockDim.x + threadIdx.x;
    const int row = idx >> 9;
    const int c   = (idx & 511) * 2;
    const float2 xv = *reinterpret_cast<const float2*>(src + (long)row * lds + c);
    uint32_t h, l;
    split2(xv.x, xv.y, h, l);
    *(uint32_t*)&hi[(long)row * ldd + c] = h;
    *(uint32_t*)&lo[(long)row * ldd + c] = l;
}

// ---------------- pure-bf16 3-product GEMM, 2-stage cp.async ----------------
// MODE 0: plain fp32 C.  MODE 1: QKV epilogue (q->rope(table)+split, k->fp32, v->split).
#define GA_ELE 5120   // 128*40
#define GB_ELE 4352   // 32*136
#define GSTAGE (2 * GA_ELE + 2 * GB_ELE)

template <int MODE>
__global__ __launch_bounds__(256)
void gemm_bf16p(const __nv_bfloat16* __restrict__ Ahi,
                const __nv_bfloat16* __restrict__ Alo,
                const __nv_bfloat16* __restrict__ Bhi,
                const __nv_bfloat16* __restrict__ Blo,
                float* __restrict__ C,
                int K, int lda, int ldb, int ldc,
                const float* __restrict__ rc,
                const float* __restrict__ rs,
                __nv_bfloat16* __restrict__ qhi,
                __nv_bfloat16* __restrict__ qlo,
                __nv_bfloat16* __restrict__ vhi,
                __nv_bfloat16* __restrict__ vlo) {
    extern __shared__ __align__(16) __nv_bfloat16 gsm[];

    const int tid  = threadIdx.x;
    const int lane = tid & 31;
    const int wid  = tid >> 5;
    const int wm   = wid >> 2;
    const int wn   = wid & 3;
    const int brow = blockIdx.y * 128;
    const int bcol = blockIdx.x * 128;

    float d[4][4][4];
#pragma unroll
    for (int i = 0; i < 4; i++)
#pragma unroll
        for (int j = 0; j < 4; j++)
#pragma unroll
            for (int r = 0; r < 4; r++) d[i][j][r] = 0.f;

    const int niter = K / 32;

    auto load_stage = [&](int kt, int st) {
        __nv_bfloat16* As_hi = gsm + st * GSTAGE;
        __nv_bfloat16* As_lo = As_hi + GA_ELE;
        __nv_bfloat16* Bs_hi = As_lo + GA_ELE;
        __nv_bfloat16* Bs_lo = Bs_hi + GB_ELE;
        const int k0 = kt * 32;
#pragma unroll
        for (int t = 0; t < 2; t++) {
            const int p  = tid + t * 256;
            const int ar = p >> 2, ac = (p & 3) * 8;
            CP16(s2u(As_hi + ar * 40 + ac), Ahi + (long)(brow + ar) * lda + k0 + ac);
            CP16(s2u(As_lo + ar * 40 + ac), Alo + (long)(brow + ar) * lda + k0 + ac);
            const int br = p >> 4, bc = (p & 15) * 8;
            CP16(s2u(Bs_hi + br * 136 + bc), Bhi + (long)(k0 + br) * ldb + bcol + bc);
            CP16(s2u(Bs_lo + br * 136 + bc), Blo + (long)(k0 + br) * ldb + bcol + bc);
        }
    };

    load_stage(0, 0);
    CPCOMMIT();

    for (int kt = 0; kt < niter; kt++) {
        if (kt + 1 < niter) {
            load_stage(kt + 1, (kt + 1) & 1);
            CPCOMMIT();
            CPWAIT(1);
        } else {
            CPWAIT(0);
        }
        __syncthreads();

        const __nv_bfloat16* As_hi = gsm + (kt & 1) * GSTAGE;
        const __nv_bfloat16* As_lo = As_hi + GA_ELE;
        const __nv_bfloat16* Bs_hi = As_lo + GA_ELE;
        const __nv_bfloat16* Bs_lo = Bs_hi + GB_ELE;
        const int g  = lane >> 3;
        const int ri = lane & 7;

#pragma unroll
        for (int kk = 0; kk < 32; kk += 16) {
            uint32_t a_hi[4][4], a_lo[4][4], b_hi[2][4], b_lo[2][4];
#pragma unroll
            for (int mi = 0; mi < 4; mi++) {
                const int row   = wm * 64 + mi * 16 + (g & 1) * 8 + ri;
                const int chunk = (kk >> 3) + (g >> 1);
                LDSM4(a_hi[mi], s2u(As_hi) + row * 80 + chunk * 16);
                LDSM4(a_lo[mi], s2u(As_lo) + row * 80 + chunk * 16);
            }
#pragma unroll
            for (int nj2 = 0; nj2 < 2; nj2++) {
                const int krow = kk + (g & 1) * 8 + ri;
                const int col  = wn * 32 + nj2 * 16 + (g >> 1) * 8;
                LDSM4T(b_hi[nj2], s2u(Bs_hi) + krow * 272 + col * 2);
                LDSM4T(b_lo[nj2], s2u(Bs_lo) + krow * 272 + col * 2);
            }
#pragma unroll
            for (int mi = 0; mi < 4; mi++)
#pragma unroll
                for (int nj = 0; nj < 4; nj++) {
                    const int nj2 = nj >> 1, u = (nj & 1) * 2;
                    MMA_BF16(d[mi][nj], a_hi[mi], b_hi[nj2] + u);
                    MMA_BF16(d[mi][nj], a_hi[mi], b_lo[nj2] + u);
                    MMA_BF16(d[mi][nj], a_lo[mi], b_hi[nj2] + u);
                }
        }
        __syncthreads();
    }

    // epilogue
#pragma unroll
    for (int mi = 0; mi < 4; mi++)
#pragma unroll
        for (int nj = 0; nj < 4; nj++) {
            const int r  = brow + wm * 64 + mi * 16 + (lane >> 2);
            const int cc = bcol + wn * 32 + nj * 8 + (lane & 3) * 2;
            float2 t0, t1;
            t0.x = d[mi][nj][0]; t0.y = d[mi][nj][1];
            t1.x = d[mi][nj][2]; t1.y = d[mi][nj][3];
            if (MODE == 0) {
                *reinterpret_cast<float2*>(C + (long)r * ldc + cc)       = t0;
                *reinterpret_cast<float2*>(C + (long)(r + 8) * ldc + cc) = t1;
            } else {
                if (cc < DIM) {               // Q: rope (table) + scale + split
                    float y0, y1;
                    uint32_t h, l;
                    rope_pair_tab(rc, rs, r, cc, t0, 0.125f, y0, y1);
                    split2(y0, y1, h, l);
                    *(uint32_t*)&qhi[(long)r * DIM + cc] = h;
                    *(uint32_t*)&qlo[(long)r * DIM + cc] = l;
                    rope_pair_tab(rc, rs, r + 8, cc, t1, 0.125f, y0, y1);
                    split2(y0, y1, h, l);
                    *(uint32_t*)&qhi[(long)(r + 8) * DIM + cc] = h;
                    *(uint32_t*)&qlo[(long)(r + 8) * DIM + cc] = l;
                } else if (cc < 2 * DIM) {    // K: fp32 for bilinear
                    *reinterpret_cast<float2*>(C + (long)r * ldc + cc)       = t0;
                    *reinterpret_cast<float2*>(C + (long)(r + 8) * ldc + cc) = t1;
                } else {                      // V: split
                    const int vc = cc - 2 * DIM;
                    uint32_t h, l;
                    split2(t0.x, t0.y, h, l);
                    *(uint32_t*)&vhi[(long)r * DIM + vc] = h;
                    *(uint32_t*)&vlo[(long)r * DIM + vc] = l;
                    split2(t1.x, t1.y, h, l);
                    *(uint32_t*)&vhi[(long)(r + 8) * DIM + vc] = h;
                    *(uint32_t*)&vlo[(long)(r + 8) * DIM + vc] = l;
                }
            }
        }
}

// ---------------- bilinear K transform with fused RoPE (table), split output ----------------
__global__ void bilinear_kernel(const float* __restrict__ k, int ldk,
                                const float* __restrict__ Wb,
                                const float* __restrict__ rc,
                                const float* __restrict__ rs,
                                __nv_bfloat16* __restrict__ kthi,
                                __nv_bfloat16* __restrict__ ktlo) {
    const int h = blockIdx.y;
    const int rowbase = blockIdx.x * 64;
    __shared__ float Wbs[64][64];
    __shared__ float ks[64][65];
    for (int p = threadIdx.x; p < 64 * 64; p += 256)
        Wbs[p / 64][p % 64] = Wb[h * 4096 + p];
    for (int p = threadIdx.x; p < 64 * 32; p += 256) {
        const int r  = p >> 5;
        const int dd = (p & 31) * 2;
        const float2 kv = *reinterpret_cast<const float2*>(
            k + (long)(rowbase + r) * ldk + h * 64 + dd);
        float y0, y1;
        rope_pair_tab(rc, rs, rowbase + r, dd, kv, 1.0f, y0, y1);
        ks[r][dd]     = y0;
        ks[r][dd + 1] = y1;
    }
    __syncthreads();
    for (int p = threadIdx.x; p < 64 * 64; p += 256) {
        const int e = p / 64, r = p % 64;
        float s = 0.f;
#pragma unroll
        for (int dd = 0; dd < 64; dd++) s = fmaf(ks[r][dd], Wbs[dd][e], s);
        const long o = ((long)h * 64 + e) * NTOK + rowbase + r;
        const __nv_bfloat16 bh = __float2bfloat16_rn(s);
        kthi[o] = bh;
        ktlo[o] = __float2bfloat16_rn(s - __bfloat162float(bh));
    }
}

// ---------------- tensor-core flash attention (R12 proven version) ----------------
#define FSTR   72
#define FCHUNK (64 * FSTR)
__global__ __launch_bounds__(256)
void flash_mma(const __nv_bfloat16* __restrict__ qhi,
               const __nv_bfloat16* __restrict__ qlo,
               const __nv_bfloat16* __restrict__ kthi,
               const __nv_bfloat16* __restrict__ ktlo,
               const __nv_bfloat16* __restrict__ vhi,
               const __nv_bfloat16* __restrict__ vlo,
               __nv_bfloat16* __restrict__ aohi,
               __nv_bfloat16* __restrict__ aolo) {
    extern __shared__ __align__(16) __nv_bfloat16 fsm[];
    __nv_bfloat16* KH = fsm;
    __nv_bfloat16* KL = fsm + 2 * FCHUNK;
    __nv_bfloat16* VH = fsm + 4 * FCHUNK;
    __nv_bfloat16* VL = fsm + 6 * FCHUNK;

    const int h     = blockIdx.y;
    const int qbase = blockIdx.x * 128;
    const int tid   = threadIdx.x;
    const int lane  = tid & 31;
    const int w     = tid >> 5;
    const int g     = lane >> 3;
    const int ri    = lane & 7;

    for (int p = tid; p < 128 * 8; p += 256) {
        const int i = p >> 3, ec = (p & 7) * 8;
        const long go = (long)(qbase + i) * DIM + h * 64 + ec;
        *(uint4*)&KH[i * FSTR + ec] = *(const uint4*)&qhi[go];
        *(uint4*)&KL[i * FSTR + ec] = *(const uint4*)&qlo[go];
    }
    __syncthreads();

    uint32_t aq_hi[4][4], aq_lo[4][4];
    {
        const int row = w * 16 + (g & 1) * 8 + ri;
#pragma unroll
        for (int kc = 0; kc < 4; kc++) {
            const int colb = (kc * 16 + (g >> 1) * 8) * 2;
            LDSM4(aq_hi[kc], s2u(KH) + row * (FSTR * 2) + colb);
            LDSM4(aq_lo[kc], s2u(KL) + row * (FSTR * 2) + colb);
        }
    }
    __syncthreads();

    auto load_kv = [&](int j0, int st) {
        __nv_bfloat16* kh = KH + st * FCHUNK;
        __nv_bfloat16* kl = KL + st * FCHUNK;
        __nv_bfloat16* vh = VH + st * FCHUNK;
        __nv_bfloat16* vl = VL + st * FCHUNK;
#pragma unroll
        for (int t = 0; t < 2; t++) {
            const int p = tid + t * 256;
            const int e = p >> 3, jc = (p & 7) * 8;
            CP16(s2u(kh + e * FSTR + jc), kthi + ((long)h * 64 + e) * NTOK + j0 + jc);
            CP16(s2u(kl + e * FSTR + jc), ktlo + ((long)h * 64 + e) * NTOK + j0 + jc);
            CP16(s2u(vh + e * FSTR + jc), vhi + (long)(j0 + e) * DIM + h * 64 + jc);
            CP16(s2u(vl + e * FSTR + jc), vlo + (long)(j0 + e) * DIM + h * 64 + jc);
        }
    };

    float o[8][4];
    float m0 = -3.4e38f, m1 = -3.4e38f, l0 = 0.f, l1 = 0.f;
#pragma unroll
    for (int t = 0; t < 8; t++)
#pragma unroll
        for (int r = 0; r < 4; r++) o[t][r] = 0.f;

    load_kv(0, 0);
    CPCOMMIT();

    for (int it = 0; it < NTOK / 64; it++) {
        if (it + 1 < NTOK / 64) {
            load_kv((it + 1) * 64, (it + 1) & 1);
            CPCOMMIT();
            CPWAIT(1);
        } else {
            CPWAIT(0);
        }
        __syncthreads();

        const __nv_bfloat16* kh = KH + (it & 1) * FCHUNK;
        const __nv_bfloat16* kl = KL + (it & 1) * FCHUNK;
        const __nv_bfloat16* vh = VH + (it & 1) * FCHUNK;
        const __nv_bfloat16* vl = VL + (it & 1) * FCHUNK;

        float s[8][4];
#pragma unroll
        for (int t = 0; t < 8; t++)
#pragma unroll
            for (int r = 0; r < 4; r++) s[t][r] = 0.f;
#pragma unroll
        for (int kc = 0; kc < 4; kc++) {
            const int krow = kc * 16 + (g & 1) * 8 + ri;
#pragma unroll
            for (int ng = 0; ng < 4; ng++) {
                uint32_t bh[4], bl[4];
                const int colb = (ng * 16 + (g >> 1) * 8) * 2;
                LDSM4T(bh, s2u(kh) + krow * (FSTR * 2) + colb);
                LDSM4T(bl, s2u(kl) + krow * (FSTR * 2) + colb);
                MMA_BF16(s[2 * ng],     aq_hi[kc], bh);
                MMA_BF16(s[2 * ng],     aq_hi[kc], bl);
                MMA_BF16(s[2 * ng],     aq_lo[kc], bh);
                MMA_BF16(s[2 * ng + 1], aq_hi[kc], bh + 2);
                MMA_BF16(s[2 * ng + 1], aq_hi[kc], bl + 2);
                MMA_BF16(s[2 * ng + 1], aq_lo[kc], bh + 2);
            }
        }

        float mx0 = -3.4e38f, mx1 = -3.4e38f;
#pragma unroll
        for (int t = 0; t < 8; t++) {
            mx0 = fmaxf(mx0, fmaxf(s[t][0], s[t][1]));
            mx1 = fmaxf(mx1, fmaxf(s[t][2], s[t][3]));
        }
        mx0 = fmaxf(mx0, __shfl_xor_sync(0xffffffffu, mx0, 1));
        mx0 = fmaxf(mx0, __shfl_xor_sync(0xffffffffu, mx0, 2));
        mx1 = fmaxf(mx1, __shfl_xor_sync(0xffffffffu, mx1, 1));
        mx1 = fmaxf(mx1, __shfl_xor_sync(0xffffffffu, mx1, 2));
        const float mn0 = fmaxf(m0, mx0);
        const float mn1 = fmaxf(m1, mx1);
        const float c0  = __expf(m0 - mn0);
        const float c1  = __expf(m1 - mn1);
        m0 = mn0; m1 = mn1;
        float rs0 = 0.f, rs1 = 0.f;
#pragma unroll
        for (int t = 0; t < 8; t++) {
            s[t][0] = __expf(s[t][0] - mn0);
            s[t][1] = __expf(s[t][1] - mn0);
            s[t][2] = __expf(s[t][2] - mn1);
            s[t][3] = __expf(s[t][3] - mn1);
            rs0 += s[t][0] + s[t][1];
            rs1 += s[t][2] + s[t][3];
        }
        rs0 += __shfl_xor_sync(0xffffffffu, rs0, 1);
        rs0 += __shfl_xor_sync(0xffffffffu, rs0, 2);
        rs1 += __shfl_xor_sync(0xffffffffu, rs1, 1);
        rs1 += __shfl_xor_sync(0xffffffffu, rs1, 2);
        l0 = l0 * c0 + rs0;
        l1 = l1 * c1 + rs1;
#pragma unroll
        for (int t = 0; t < 8; t++) {
            o[t][0] *= c0; o[t][1] *= c0;
            o[t][2] *= c1; o[t][3] *= c1;
        }

        uint32_t ap_hi[4][4], ap_lo[4][4];
#pragma unroll
        for (int c = 0; c < 4; c++) {
            split2(s[2 * c][0],     s[2 * c][1],     ap_hi[c][0], ap_lo[c][0]);
            split2(s[2 * c][2],     s[2 * c][3],     ap_hi[c][1], ap_lo[c][1]);
            split2(s[2 * c + 1][0], s[2 * c + 1][1], ap_hi[c][2], ap_lo[c][2]);
            split2(s[2 * c + 1][2], s[2 * c + 1][3], ap_hi[c][3], ap_lo[c][3]);
        }

#pragma unroll
        for (int kc = 0; kc < 4; kc++) {
            const int krow = kc * 16 + (g & 1) * 8 + ri;
#pragma unroll
            for (int ng = 0; ng < 4; ng++) {
                uint32_t bh[4], bl[4];
                const int colb = (ng * 16 + (g >> 1) * 8) * 2;
                LDSM4T(bh, s2u(vh) + krow * (FSTR * 2) + colb);
                LDSM4T(bl, s2u(vl) + krow * (FSTR * 2) + colb);
                MMA_BF16(o[2 * ng],     ap_hi[kc], bh);
                MMA_BF16(o[2 * ng],     ap_hi[kc], bl);
                MMA_BF16(o[2 * ng],     ap_lo[kc], bh);
                MMA_BF16(o[2 * ng + 1], ap_hi[kc], bh + 2);
                MMA_BF16(o[2 * ng + 1], ap_hi[kc], bl + 2);
                MMA_BF16(o[2 * ng + 1], ap_lo[kc], bh + 2);
            }
        }
        __syncthreads();
    }

    const float i0 = 1.f / l0;
    const float i1 = 1.f / l1;
    const int r  = qbase + w * 16 + (lane >> 2);
#pragma unroll
    for (int t = 0; t < 8; t++) {
        const int cc = h * 64 + t * 8 + (lane & 3) * 2;
        uint32_t h0, l0u, h1, l1u;
        split2(o[t][0] * i0, o[t][1] * i0, h0, l0u);
        split2(o[t][2] * i1, o[t][3] * i1, h1, l1u);
        *(uint32_t*)&aohi[(long)r * DIM + cc]       = h0;
        *(uint32_t*)&aolo[(long)r * DIM + cc]       = l0u;
        *(uint32_t*)&aohi[(long)(r + 8) * DIM + cc] = h1;
        *(uint32_t*)&aolo[(long)(r + 8) * DIM + cc] = l1u;
    }
}

// ---------------- launch ----------------
extern "C" void kernel_launch(void* const* d_in, const int* in_sizes, int n_in,
                              void* d_out, int out_size) {
    const float* x     = (const float*)d_in[0];
    const float* gamma = (const float*)d_in[1];
    const float* Wq    = (const float*)d_in[2];
    const float* Wkv   = (const float*)d_in[3];
    const float* Wb    = (const float*)d_in[4];
    const float* Wo    = (const float*)d_in[5];
    float* out = (float*)d_out;

    float *qkv, *rc, *rs;
    __nv_bfloat16 *xn_hi, *xn_lo, *wqkv_hi, *wqkv_lo, *wo_hi, *wo_lo;
    __nv_bfloat16 *q_hi, *q_lo, *kt_hi, *kt_lo, *v_hi, *v_lo, *ao_hi, *ao_lo;
    cudaGetSymbolAddress((void**)&qkv,     g_qkv);
    cudaGetSymbolAddress((void**)&rc,      g_rc);
    cudaGetSymbolAddress((void**)&rs,      g_rs);
    cudaGetSymbolAddress((void**)&xn_hi,   g_xn_hi);
    cudaGetSymbolAddress((void**)&xn_lo,   g_xn_lo);
    cudaGetSymbolAddress((void**)&wqkv_hi, g_wqkv_hi);
    cudaGetSymbolAddress((void**)&wqkv_lo, g_wqkv_lo);
    cudaGetSymbolAddress((void**)&wo_hi,   g_wo_hi);
    cudaGetSymbolAddress((void**)&wo_lo,   g_wo_lo);
    cudaGetSymbolAddress((void**)&q_hi,    g_q_hi);
    cudaGetSymbolAddress((void**)&q_lo,    g_q_lo);
    cudaGetSymbolAddress((void**)&kt_hi,   g_kt_hi);
    cudaGetSymbolAddress((void**)&kt_lo,   g_kt_lo);
    cudaGetSymbolAddress((void**)&v_hi,    g_v_hi);
    cudaGetSymbolAddress((void**)&v_lo,    g_v_lo);
    cudaGetSymbolAddress((void**)&ao_hi,   g_ao_hi);
    cudaGetSymbolAddress((void**)&ao_lo,   g_ao_lo);

    float* k = qkv + DIM;

    const int gemm_smem = GSTAGE * 2 * (int)sizeof(__nv_bfloat16);   // 75776
    const int flash_smem = 8 * FCHUNK * (int)sizeof(__nv_bfloat16);  // 73728
    cudaFuncSetAttribute(gemm_bf16p<0>,
                         cudaFuncAttributeMaxDynamicSharedMemorySize, gemm_smem);
    cudaFuncSetAttribute(gemm_bf16p<1>,
                         cudaFuncAttributeMaxDynamicSharedMemorySize, gemm_smem);
    cudaFuncSetAttribute(flash_mma,
                         cudaFuncAttributeMaxDynamicSharedMemorySize, flash_smem);

    // 0. rope tables (independent of everything)
    rope_tab<<<NTOK * 32 / 256, 256>>>(rc, rs);

    // 1. LayerNorm -> split bf16
    ln_kernel<<<NTOK, 256>>>(x, gamma, xn_hi, xn_lo);

    // 1b. weight splits (independent)
    wsplit_qkv<<<dim3(QKV_LD / 512, DIM), 256>>>(Wq, Wkv, wqkv_hi, wqkv_lo);
    split_kernel<<<DIM * 512 / 256, 256>>>(Wo, DIM, wo_hi, wo_lo, DIM);

    // 2. qkv = xn @ [Wq | Wkv] with fused epilogue (q rope+split, k fp32, v split)
    gemm_bf16p<1><<<dim3(QKV_LD / 128, NTOK / 128), 256, gemm_smem>>>(
        xn_hi, xn_lo, wqkv_hi, wqkv_lo, qkv, DIM, DIM, QKV_LD, QKV_LD,
        rc, rs, q_hi, q_lo, v_hi, v_lo);

    // 3. bilinear K transform (RoPE via table) -> kt hi/lo [h][e][n]
    bilinear_kernel<<<dim3(NTOK / 64, NHEADS), 256>>>(
        k, QKV_LD, Wb, rc, rs, kt_hi, kt_lo);

    // 4. flash attention -> ao split bf16
    flash_mma<<<dim3(NTOK / 128, NHEADS), 256, flash_smem>>>(
        q_hi, q_lo, kt_hi, kt_lo, v_hi, v_lo, ao_hi, ao_lo);

    // 5. out = ao @ Wo
    gemm_bf16p<0><<<dim3(DIM / 128, NTOK / 128), 256, gemm_smem>>>(
        ao_hi, ao_lo, wo_hi, wo_lo, out, DIM, DIM, DIM, DIM,
        nullptr, nullptr, nullptr, nullptr, nullptr, nullptr);
}

// round 15
// speedup vs baseline: 1.1008x; 1.0158x over previous
#include <cuda_runtime.h>
#include <cuda_bf16.h>
#include <math.h>
#include <stdint.h>

#define NTOK   2048
#define DIM    1024
#define NHEADS 16
#define DHEAD  64
#define QKV_LD 3072

// ---------------- scratch (no allocations allowed) ----------------
__device__ float g_qkv [NTOK * QKV_LD];          // q | k fp32 (v never stored fp32)
__device__ float g_rc  [NTOK * 32];              // rope cos table [pos][j]
__device__ float g_rs  [NTOK * 32];              // rope sin table [pos][j]
__device__ __nv_bfloat16 g_xn_hi[NTOK * DIM];
__device__ __nv_bfloat16 g_xn_lo[NTOK * DIM];
__device__ __nv_bfloat16 g_wqkv_hi[DIM * QKV_LD];
__device__ __nv_bfloat16 g_wqkv_lo[DIM * QKV_LD];
__device__ __nv_bfloat16 g_wo_hi[DIM * DIM];
__device__ __nv_bfloat16 g_wo_lo[DIM * DIM];
__device__ __nv_bfloat16 g_q_hi [NTOK * DIM];
__device__ __nv_bfloat16 g_q_lo [NTOK * DIM];
__device__ __nv_bfloat16 g_kt_hi[NHEADS * DHEAD * NTOK];  // [h][e][n]
__device__ __nv_bfloat16 g_kt_lo[NHEADS * DHEAD * NTOK];
__device__ __nv_bfloat16 g_v_hi [NTOK * DIM];
__device__ __nv_bfloat16 g_v_lo [NTOK * DIM];
__device__ __nv_bfloat16 g_ao_hi[NTOK * DIM];
__device__ __nv_bfloat16 g_ao_lo[NTOK * DIM];

static __device__ __forceinline__ uint32_t s2u(const void* p) {
    return (uint32_t)__cvta_generic_to_shared(p);
}

#define LDSM4(R, addr) \
    asm volatile("ldmatrix.sync.aligned.m8n8.x4.shared.b16 {%0,%1,%2,%3},[%4];" \
        : "=r"((R)[0]), "=r"((R)[1]), "=r"((R)[2]), "=r"((R)[3]) : "r"(addr))
#define LDSM4T(R, addr) \
    asm volatile("ldmatrix.sync.aligned.m8n8.x4.trans.shared.b16 {%0,%1,%2,%3},[%4];" \
        : "=r"((R)[0]), "=r"((R)[1]), "=r"((R)[2]), "=r"((R)[3]) : "r"(addr))
#define MMA_BF16(D, A, B) \
    asm volatile("mma.sync.aligned.m16n8k16.row.col.f32.bf16.bf16.f32 " \
        "{%0,%1,%2,%3},{%4,%5,%6,%7},{%8,%9},{%0,%1,%2,%3};" \
        : "+f"((D)[0]), "+f"((D)[1]), "+f"((D)[2]), "+f"((D)[3]) \
        : "r"((A)[0]), "r"((A)[1]), "r"((A)[2]), "r"((A)[3]), "r"((B)[0]), "r"((B)[1]))
#define CP16(dst, src) \
    asm volatile("cp.async.ca.shared.global [%0],[%1],16;" :: "r"(dst), "l"(src))
#define CPCOMMIT() asm volatile("cp.async.commit_group;")
#define CPWAIT(n)  asm volatile("cp.async.wait_group %0;" :: "n"(n))

static __device__ __forceinline__ void split2(float x, float y,
                                              uint32_t& hi, uint32_t& lo) {
    float2 f; f.x = x; f.y = y;
    __nv_bfloat162 h = __float22bfloat162_rn(f);
    float2 hf = __bfloat1622float2(h);
    float2 r; r.x = x - hf.x; r.y = y - hf.y;
    __nv_bfloat162 l = __float22bfloat162_rn(r);
    hi = *(uint32_t*)&h; lo = *(uint32_t*)&l;
}

// ---------------- rope table generation (accurate cosf/sinf, one-off) ----------------
__global__ void rope_tab(float* __restrict__ rc, float* __restrict__ rs) {
    const int idx = blockIdx.x * blockDim.x + threadIdx.x;  // NTOK*32
    const int pos = idx >> 5;
    const int j   = idx & 31;
    const float th = powf(10000.f, -(float)j * (1.f / 32.f));
    const float a  = (float)pos * th;
    rc[idx] = cosf(a);
    rs[idx] = sinf(a);
}

// ---------------- table-based RoPE pair ----------------
__device__ __forceinline__ void rope_pair_tab(const float* __restrict__ rc,
                                              const float* __restrict__ rs,
                                              int row, int c, const float2 xv,
                                              float scale, float& y0, float& y1) {
    const int dd = c & 63;                       // even in [0,62]
    const int i0 = (dd < 32) ? dd : dd - 32;
    const int i1 = (dd + 1 < 32) ? dd + 1 : dd - 31;
    const float c0 = rc[row * 32 + i0], s0 = rs[row * 32 + i0];
    const float c1 = rc[row * 32 + i1], s1 = rs[row * 32 + i1];
    y0 = (xv.x * c0 - xv.y * s0) * scale;
    y1 = (xv.y * c1 + xv.x * s1) * scale;
}

// ---------------- LayerNorm -> split bf16 ----------------
__global__ void ln_kernel(const float* __restrict__ x,
                          const float* __restrict__ gamma,
                          __nv_bfloat16* __restrict__ xhi,
                          __nv_bfloat16* __restrict__ xlo) {
    __shared__ float red[16];
    const int row = blockIdx.x;
    const float2* xr = reinterpret_cast<const float2*>(x + (long)row * DIM);
    float2 v[2];
    float s = 0.f, ss = 0.f;
#pragma unroll
    for (int i = 0; i < 2; i++) {
        v[i] = xr[threadIdx.x + i * 256];
        s += v[i].x + v[i].y;
        ss += v[i].x * v[i].x + v[i].y * v[i].y;
    }
#pragma unroll
    for (int o = 16; o > 0; o >>= 1) {
        s  += __shfl_xor_sync(0xffffffffu, s,  o);
        ss += __shfl_xor_sync(0xffffffffu, ss, o);
    }
    if ((threadIdx.x & 31) == 0) {
        red[threadIdx.x >> 5]       = s;
        red[8 + (threadIdx.x >> 5)] = ss;
    }
    __syncthreads();
    s = red[0]; ss = red[8];
#pragma unroll
    for (int i = 1; i < 8; i++) { s += red[i]; ss += red[8 + i]; }
    const float mu  = s * (1.f / DIM);
    const float var = ss * (1.f / DIM) - mu * mu;
    const float inv = rsqrtf(var + 1e-5f);
    const float2* g2 = reinterpret_cast<const float2*>(gamma);
#pragma unroll
    for (int i = 0; i < 2; i++) {
        const int p = threadIdx.x + i * 256;
        const float2 gg = g2[p];
        const float y0 = (v[i].x - mu) * inv * gg.x;
        const float y1 = (v[i].y - mu) * inv * gg.y;
        uint32_t h, l;
        split2(y0, y1, h, l);
        *(uint32_t*)&xhi[(long)row * DIM + 2 * p] = h;
        *(uint32_t*)&xlo[(long)row * DIM + 2 * p] = l;
    }
}

// ---------------- merged weight split: [Wq | Wkv | Wo] ----------------
__global__ void wsplit_all(const float* __restrict__ Wq,
                           const float* __restrict__ Wkv,
                           const float* __restrict__ Wo,
                           __nv_bfloat16* __restrict__ qkvhi,
                           __nv_bfloat16* __restrict__ qkvlo,
                           __nv_bfloat16* __restrict__ wohi,
                           __nv_bfloat16* __restrict__ wolo) {
    const int r = blockIdx.y;
    const int c = (blockIdx.x * blockDim.x + threadIdx.x) * 2;   // [0, 4096)
    float2 v;
    uint32_t h, l;
    if (c < DIM) {
        v = *reinterpret_cast<const float2*>(Wq + (long)r * DIM + c);
        split2(v.x, v.y, h, l);
        *(uint32_t*)&qkvhi[(long)r * QKV_LD + c] = h;
        *(uint32_t*)&qkvlo[(long)r * QKV_LD + c] = l;
    } else if (c < 3 * DIM) {
        v = *reinterpret_cast<const float2*>(Wkv + (long)r * 2 * DIM + (c - DIM));
        split2(v.x, v.y, h, l);
        *(uint32_t*)&qkvhi[(long)r * QKV_LD + c] = h;
        *(uint32_t*)&qkvlo[(long)r * QKV_LD + c] = l;
    } else {
        const int oc = c - 3 * DIM;
        v = *reinterpret_cast<const float2*>(Wo + (long)r * DIM + oc);
        split2(v.x, v.y, h, l);
        *(uint32_t*)&wohi[(long)r * DIM + oc] = h;
        *(uint32_t*)&wolo[(long)r * DIM + oc] = l;
    }
}

// ---------------- rope+split q (table-based, bandwidth-bound) ----------------
__global__ void rope_split_q(const float* __restrict__ qkv,
                             const float* __restrict__ rc,
                             const float* __restrict__ rs,
                             __nv_bfloat16* __restrict__ qhi,
                             __nv_bfloat16* __restrict__ qlo) {
    const int idx = blockIdx.x * blockDim.x + threadIdx.x;  // NTOK*512 pairs
    const int row = idx >> 9;
    const int c   = (idx & 511) * 2;
    const float2 xv = *reinterpret_cast<const float2*>(qkv + (long)row * QKV_LD + c);
    float y0, y1;
    rope_pair_tab(rc, rs, row, c, xv, 0.125f, y0, y1);
    uint32_t h, l;
    split2(y0, y1, h, l);
    *(uint32_t*)&qhi[(long)row * DIM + c] = h;
    *(uint32_t*)&qlo[(long)row * DIM + c] = l;
}

// ---------------- pure-bf16 3-product GEMM, 2-stage cp.async ----------------
// MODE 0: plain fp32 C.  MODE 1: cc<2048 plain fp32 (q,k); cc>=2048 v-split.
#define GA_ELE 5120   // 128*40
#define GB_ELE 4352   // 32*136
#define GSTAGE (2 * GA_ELE + 2 * GB_ELE)

template <int MODE>
__global__ __launch_bounds__(256)
void gemm_bf16p(const __nv_bfloat16* __restrict__ Ahi,
                const __nv_bfloat16* __restrict__ Alo,
                const __nv_bfloat16* __restrict__ Bhi,
                const __nv_bfloat16* __restrict__ Blo,
                float* __restrict__ C,
                int K, int lda, int ldb, int ldc,
                __nv_bfloat16* __restrict__ vhi,
                __nv_bfloat16* __restrict__ vlo) {
    extern __shared__ __align__(16) __nv_bfloat16 gsm[];

    const int tid  = threadIdx.x;
    const int lane = tid & 31;
    const int wid  = tid >> 5;
    const int wm   = wid >> 2;
    const int wn   = wid & 3;
    const int brow = blockIdx.y * 128;
    const int bcol = blockIdx.x * 128;

    float d[4][4][4];
#pragma unroll
    for (int i = 0; i < 4; i++)
#pragma unroll
        for (int j = 0; j < 4; j++)
#pragma unroll
            for (int r = 0; r < 4; r++) d[i][j][r] = 0.f;

    const int niter = K / 32;

    auto load_stage = [&](int kt, int st) {
        __nv_bfloat16* As_hi = gsm + st * GSTAGE;
        __nv_bfloat16* As_lo = As_hi + GA_ELE;
        __nv_bfloat16* Bs_hi = As_lo + GA_ELE;
        __nv_bfloat16* Bs_lo = Bs_hi + GB_ELE;
        const int k0 = kt * 32;
#pragma unroll
        for (int t = 0; t < 2; t++) {
            const int p  = tid + t * 256;
            const int ar = p >> 2, ac = (p & 3) * 8;
            CP16(s2u(As_hi + ar * 40 + ac), Ahi + (long)(brow + ar) * lda + k0 + ac);
            CP16(s2u(As_lo + ar * 40 + ac), Alo + (long)(brow + ar) * lda + k0 + ac);
            const int br = p >> 4, bc = (p & 15) * 8;
            CP16(s2u(Bs_hi + br * 136 + bc), Bhi + (long)(k0 + br) * ldb + bcol + bc);
            CP16(s2u(Bs_lo + br * 136 + bc), Blo + (long)(k0 + br) * ldb + bcol + bc);
        }
    };

    load_stage(0, 0);
    CPCOMMIT();

    for (int kt = 0; kt < niter; kt++) {
        if (kt + 1 < niter) {
            load_stage(kt + 1, (kt + 1) & 1);
            CPCOMMIT();
            CPWAIT(1);
        } else {
            CPWAIT(0);
        }
        __syncthreads();

        const __nv_bfloat16* As_hi = gsm + (kt & 1) * GSTAGE;
        const __nv_bfloat16* As_lo = As_hi + GA_ELE;
        const __nv_bfloat16* Bs_hi = As_lo + GA_ELE;
        const __nv_bfloat16* Bs_lo = Bs_hi + GB_ELE;
        const int g  = lane >> 3;
        const int ri = lane & 7;

#pragma unroll
        for (int kk = 0; kk < 32; kk += 16) {
            uint32_t a_hi[4][4], a_lo[4][4], b_hi[2][4], b_lo[2][4];
#pragma unroll
            for (int mi = 0; mi < 4; mi++) {
                const int row   = wm * 64 + mi * 16 + (g & 1) * 8 + ri;
                const int chunk = (kk >> 3) + (g >> 1);
                LDSM4(a_hi[mi], s2u(As_hi) + row * 80 + chunk * 16);
                LDSM4(a_lo[mi], s2u(As_lo) + row * 80 + chunk * 16);
            }
#pragma unroll
            for (int nj2 = 0; nj2 < 2; nj2++) {
                const int krow = kk + (g & 1) * 8 + ri;
                const int col  = wn * 32 + nj2 * 16 + (g >> 1) * 8;
                LDSM4T(b_hi[nj2], s2u(Bs_hi) + krow * 272 + col * 2);
                LDSM4T(b_lo[nj2], s2u(Bs_lo) + krow * 272 + col * 2);
            }
#pragma unroll
            for (int mi = 0; mi < 4; mi++)
#pragma unroll
                for (int nj = 0; nj < 4; nj++) {
                    const int nj2 = nj >> 1, u = (nj & 1) * 2;
                    MMA_BF16(d[mi][nj], a_hi[mi], b_hi[nj2] + u);
                    MMA_BF16(d[mi][nj], a_hi[mi], b_lo[nj2] + u);
                    MMA_BF16(d[mi][nj], a_lo[mi], b_hi[nj2] + u);
                }
        }
        __syncthreads();
    }

    // epilogue
#pragma unroll
    for (int mi = 0; mi < 4; mi++)
#pragma unroll
        for (int nj = 0; nj < 4; nj++) {
            const int r  = brow + wm * 64 + mi * 16 + (lane >> 2);
            const int cc = bcol + wn * 32 + nj * 8 + (lane & 3) * 2;
            float2 t0, t1;
            t0.x = d[mi][nj][0]; t0.y = d[mi][nj][1];
            t1.x = d[mi][nj][2]; t1.y = d[mi][nj][3];
            if (MODE == 0 || cc < 2 * DIM) {
                *reinterpret_cast<float2*>(C + (long)r * ldc + cc)       = t0;
                *reinterpret_cast<float2*>(C + (long)(r + 8) * ldc + cc) = t1;
            } else {                      // V: split
                const int vc = cc - 2 * DIM;
                uint32_t h, l;
                split2(t0.x, t0.y, h, l);
                *(uint32_t*)&vhi[(long)r * DIM + vc] = h;
                *(uint32_t*)&vlo[(long)r * DIM + vc] = l;
                split2(t1.x, t1.y, h, l);
                *(uint32_t*)&vhi[(long)(r + 8) * DIM + vc] = h;
                *(uint32_t*)&vlo[(long)(r + 8) * DIM + vc] = l;
            }
        }
}

// ---------------- bilinear K transform with fused RoPE (table), split output ----------------
__global__ void bilinear_kernel(const float* __restrict__ k, int ldk,
                                const float* __restrict__ Wb,
                                const float* __restrict__ rc,
                                const float* __restrict__ rs,
                                __nv_bfloat16* __restrict__ kthi,
                                __nv_bfloat16* __restrict__ ktlo) {
    const int h = blockIdx.y;
    const int rowbase = blockIdx.x * 64;
    __shared__ float Wbs[64][64];
    __shared__ float ks[64][65];
    for (int p = threadIdx.x; p < 64 * 64; p += 256)
        Wbs[p / 64][p % 64] = Wb[h * 4096 + p];
    for (int p = threadIdx.x; p < 64 * 32; p += 256) {
        const int r  = p >> 5;
        const int dd = (p & 31) * 2;
        const float2 kv = *reinterpret_cast<const float2*>(
            k + (long)(rowbase + r) * ldk + h * 64 + dd);
        float y0, y1;
        rope_pair_tab(rc, rs, rowbase + r, dd, kv, 1.0f, y0, y1);
        ks[r][dd]     = y0;
        ks[r][dd + 1] = y1;
    }
    __syncthreads();
    for (int p = threadIdx.x; p < 64 * 64; p += 256) {
        const int e = p / 64, r = p % 64;
        float s = 0.f;
#pragma unroll
        for (int dd = 0; dd < 64; dd++) s = fmaf(ks[r][dd], Wbs[dd][e], s);
        const long o = ((long)h * 64 + e) * NTOK + rowbase + r;
        const __nv_bfloat16 bh = __float2bfloat16_rn(s);
        kthi[o] = bh;
        ktlo[o] = __float2bfloat16_rn(s - __bfloat162float(bh));
    }
}

// ---------------- tensor-core flash attention ----------------
#define FSTR   72
#define FCHUNK (64 * FSTR)
__global__ __launch_bounds__(256)
void flash_mma(const __nv_bfloat16* __restrict__ qhi,
               const __nv_bfloat16* __restrict__ qlo,
               const __nv_bfloat16* __restrict__ kthi,
               const __nv_bfloat16* __restrict__ ktlo,
               const __nv_bfloat16* __restrict__ vhi,
               const __nv_bfloat16* __restrict__ vlo,
               __nv_bfloat16* __restrict__ aohi,
               __nv_bfloat16* __restrict__ aolo) {
    extern __shared__ __align__(16) __nv_bfloat16 fsm[];
    __nv_bfloat16* KH = fsm;
    __nv_bfloat16* KL = fsm + 2 * FCHUNK;
    __nv_bfloat16* VH = fsm + 4 * FCHUNK;
    __nv_bfloat16* VL = fsm + 6 * FCHUNK;

    const int h     = blockIdx.y;
    const int qbase = blockIdx.x * 128;
    const int tid   = threadIdx.x;
    const int lane  = tid & 31;
    const int w     = tid >> 5;
    const int g     = lane >> 3;
    const int ri    = lane & 7;

    for (int p = tid; p < 128 * 8; p += 256) {
        const int i = p >> 3, ec = (p & 7) * 8;
        const long go = (long)(qbase + i) * DIM + h * 64 + ec;
        *(uint4*)&KH[i * FSTR + ec] = *(const uint4*)&qhi[go];
        *(uint4*)&KL[i * FSTR + ec] = *(const uint4*)&qlo[go];
    }
    __syncthreads();

    uint32_t aq_hi[4][4], aq_lo[4][4];
    {
        const int row = w * 16 + (g & 1) * 8 + ri;
#pragma unroll
        for (int kc = 0; kc < 4; kc++) {
            const int colb = (kc * 16 + (g >> 1) * 8) * 2;
            LDSM4(aq_hi[kc], s2u(KH) + row * (FSTR * 2) + colb);
            LDSM4(aq_lo[kc], s2u(KL) + row * (FSTR * 2) + colb);
        }
    }
    __syncthreads();

    auto load_kv = [&](int j0, int st) {
        __nv_bfloat16* kh = KH + st * FCHUNK;
        __nv_bfloat16* kl = KL + st * FCHUNK;
        __nv_bfloat16* vh = VH + st * FCHUNK;
        __nv_bfloat16* vl = VL + st * FCHUNK;
#pragma unroll
        for (int t = 0; t < 2; t++) {
            const int p = tid + t * 256;
            const int e = p >> 3, jc = (p & 7) * 8;
            CP16(s2u(kh + e * FSTR + jc), kthi + ((long)h * 64 + e) * NTOK + j0 + jc);
            CP16(s2u(kl + e * FSTR + jc), ktlo + ((long)h * 64 + e) * NTOK + j0 + jc);
            CP16(s2u(vh + e * FSTR + jc), vhi + (long)(j0 + e) * DIM + h * 64 + jc);
            CP16(s2u(vl + e * FSTR + jc), vlo + (long)(j0 + e) * DIM + h * 64 + jc);
        }
    };

    float o[8][4];
    float m0 = -3.4e38f, m1 = -3.4e38f;
    float lp0 = 0.f, lp1 = 0.f;       // per-lane partial row sums
#pragma unroll
    for (int t = 0; t < 8; t++)
#pragma unroll
        for (int r = 0; r < 4; r++) o[t][r] = 0.f;

    load_kv(0, 0);
    CPCOMMIT();

    for (int it = 0; it < NTOK / 64; it++) {
        if (it + 1 < NTOK / 64) {
            load_kv((it + 1) * 64, (it + 1) & 1);
            CPCOMMIT();
            CPWAIT(1);
        } else {
            CPWAIT(0);
        }
        __syncthreads();

        const __nv_bfloat16* kh = KH + (it & 1) * FCHUNK;
        const __nv_bfloat16* kl = KL + (it & 1) * FCHUNK;
        const __nv_bfloat16* vh = VH + (it & 1) * FCHUNK;
        const __nv_bfloat16* vl = VL + (it & 1) * FCHUNK;

        float s[8][4];
#pragma unroll
        for (int t = 0; t < 8; t++)
#pragma unroll
            for (int r = 0; r < 4; r++) s[t][r] = 0.f;
#pragma unroll
        for (int kc = 0; kc < 4; kc++) {
            const int krow = kc * 16 + (g & 1) * 8 + ri;
#pragma unroll
            for (int ng = 0; ng < 4; ng++) {
                uint32_t bh[4], bl[4];
                const int colb = (ng * 16 + (g >> 1) * 8) * 2;
                LDSM4T(bh, s2u(kh) + krow * (FSTR * 2) + colb);
                LDSM4T(bl, s2u(kl) + krow * (FSTR * 2) + colb);
                MMA_BF16(s[2 * ng],     aq_hi[kc], bh);
                MMA_BF16(s[2 * ng],     aq_hi[kc], bl);
                MMA_BF16(s[2 * ng],     aq_lo[kc], bh);
                MMA_BF16(s[2 * ng + 1], aq_hi[kc], bh + 2);
                MMA_BF16(s[2 * ng + 1], aq_hi[kc], bl + 2);
                MMA_BF16(s[2 * ng + 1], aq_lo[kc], bh + 2);
            }
        }

        // ---- online softmax (max reduced per quad; sum kept per-lane) ----
        float mx0 = -3.4e38f, mx1 = -3.4e38f;
#pragma unroll
        for (int t = 0; t < 8; t++) {
            mx0 = fmaxf(mx0, fmaxf(s[t][0], s[t][1]));
            mx1 = fmaxf(mx1, fmaxf(s[t][2], s[t][3]));
        }
        mx0 = fmaxf(mx0, __shfl_xor_sync(0xffffffffu, mx0, 1));
        mx0 = fmaxf(mx0, __shfl_xor_sync(0xffffffffu, mx0, 2));
        mx1 = fmaxf(mx1, __shfl_xor_sync(0xffffffffu, mx1, 1));
        mx1 = fmaxf(mx1, __shfl_xor_sync(0xffffffffu, mx1, 2));
        const float mn0 = fmaxf(m0, mx0);
        const float mn1 = fmaxf(m1, mx1);
        const float c0  = __expf(m0 - mn0);
        const float c1  = __expf(m1 - mn1);
        m0 = mn0; m1 = mn1;
        float rs0 = 0.f, rs1 = 0.f;
#pragma unroll
        for (int t = 0; t < 8; t++) {
            s[t][0] = __expf(s[t][0] - mn0);
            s[t][1] = __expf(s[t][1] - mn0);
            s[t][2] = __expf(s[t][2] - mn1);
            s[t][3] = __expf(s[t][3] - mn1);
            rs0 += s[t][0] + s[t][1];
            rs1 += s[t][2] + s[t][3];
        }
        lp0 = lp0 * c0 + rs0;          // c0/c1 uniform across the lane quad
        lp1 = lp1 * c1 + rs1;
#pragma unroll
        for (int t = 0; t < 8; t++) {
            o[t][0] *= c0; o[t][1] *= c0;
            o[t][2] *= c1; o[t][3] *= c1;
        }

        uint32_t ap_hi[4][4], ap_lo[4][4];
#pragma unroll
        for (int c = 0; c < 4; c++) {
            split2(s[2 * c][0],     s[2 * c][1],     ap_hi[c][0], ap_lo[c][0]);
            split2(s[2 * c][2],     s[2 * c][3],     ap_hi[c][1], ap_lo[c][1]);
            split2(s[2 * c + 1][0], s[2 * c + 1][1], ap_hi[c][2], ap_lo[c][2]);
            split2(s[2 * c + 1][2], s[2 * c + 1][3], ap_hi[c][3], ap_lo[c][3]);
        }

#pragma unroll
        for (int kc = 0; kc < 4; kc++) {
            const int krow = kc * 16 + (g & 1) * 8 + ri;
#pragma unroll
            for (int ng = 0; ng < 4; ng++) {
                uint32_t bh[4], bl[4];
                const int colb = (ng * 16 + (g >> 1) * 8) * 2;
                LDSM4T(bh, s2u(vh) + krow * (FSTR * 2) + colb);
                LDSM4T(bl, s2u(vl) + krow * (FSTR * 2) + colb);
                MMA_BF16(o[2 * ng],     ap_hi[kc], bh);
                MMA_BF16(o[2 * ng],     ap_hi[kc], bl);
                MMA_BF16(o[2 * ng],     ap_lo[kc], bh);
                MMA_BF16(o[2 * ng + 1], ap_hi[kc], bh + 2);
                MMA_BF16(o[2 * ng + 1], ap_hi[kc], bl + 2);
                MMA_BF16(o[2 * ng + 1], ap_lo[kc], bh + 2);
            }
        }
        __syncthreads();
    }

    // final l reduction (2 shuffles, once)
    float l0 = lp0, l1 = lp1;
    l0 += __shfl_xor_sync(0xffffffffu, l0, 1);
    l0 += __shfl_xor_sync(0xffffffffu, l0, 2);
    l1 += __shfl_xor_sync(0xffffffffu, l1, 1);
    l1 += __shfl_xor_sync(0xffffffffu, l1, 2);

    const float i0 = 1.f / l0;
    const float i1 = 1.f / l1;
    const int r  = qbase + w * 16 + (lane >> 2);
#pragma unroll
    for (int t = 0; t < 8; t++) {
        const int cc = h * 64 + t * 8 + (lane & 3) * 2;
        uint32_t h0, l0u, h1, l1u;
        split2(o[t][0] * i0, o[t][1] * i0, h0, l0u);
        split2(o[t][2] * i1, o[t][3] * i1, h1, l1u);
        *(uint32_t*)&aohi[(long)r * DIM + cc]       = h0;
        *(uint32_t*)&aolo[(long)r * DIM + cc]       = l0u;
        *(uint32_t*)&aohi[(long)(r + 8) * DIM + cc] = h1;
        *(uint32_t*)&aolo[(long)(r + 8) * DIM + cc] = l1u;
    }
}

// ---------------- launch ----------------
extern "C" void kernel_launch(void* const* d_in, const int* in_sizes, int n_in,
                              void* d_out, int out_size) {
    const float* x     = (const float*)d_in[0];
    const float* gamma = (const float*)d_in[1];
    const float* Wq    = (const float*)d_in[2];
    const float* Wkv   = (const float*)d_in[3];
    const float* Wb    = (const float*)d_in[4];
    const float* Wo    = (const float*)d_in[5];
    float* out = (float*)d_out;

    float *qkv, *rc, *rs;
    __nv_bfloat16 *xn_hi, *xn_lo, *wqkv_hi, *wqkv_lo, *wo_hi, *wo_lo;
    __nv_bfloat16 *q_hi, *q_lo, *kt_hi, *kt_lo, *v_hi, *v_lo, *ao_hi, *ao_lo;
    cudaGetSymbolAddress((void**)&qkv,     g_qkv);
    cudaGetSymbolAddress((void**)&rc,      g_rc);
    cudaGetSymbolAddress((void**)&rs,      g_rs);
    cudaGetSymbolAddress((void**)&xn_hi,   g_xn_hi);
    cudaGetSymbolAddress((void**)&xn_lo,   g_xn_lo);
    cudaGetSymbolAddress((void**)&wqkv_hi, g_wqkv_hi);
    cudaGetSymbolAddress((void**)&wqkv_lo, g_wqkv_lo);
    cudaGetSymbolAddress((void**)&wo_hi,   g_wo_hi);
    cudaGetSymbolAddress((void**)&wo_lo,   g_wo_lo);
    cudaGetSymbolAddress((void**)&q_hi,    g_q_hi);
    cudaGetSymbolAddress((void**)&q_lo,    g_q_lo);
    cudaGetSymbolAddress((void**)&kt_hi,   g_kt_hi);
    cudaGetSymbolAddress((void**)&kt_lo,   g_kt_lo);
    cudaGetSymbolAddress((void**)&v_hi,    g_v_hi);
    cudaGetSymbolAddress((void**)&v_lo,    g_v_lo);
    cudaGetSymbolAddress((void**)&ao_hi,   g_ao_hi);
    cudaGetSymbolAddress((void**)&ao_lo,   g_ao_lo);

    float* k = qkv + DIM;

    const int gemm_smem = GSTAGE * 2 * (int)sizeof(__nv_bfloat16);   // 75776
    const int flash_smem = 8 * FCHUNK * (int)sizeof(__nv_bfloat16);  // 73728
    cudaFuncSetAttribute(gemm_bf16p<0>,
                         cudaFuncAttributeMaxDynamicSharedMemorySize, gemm_smem);
    cudaFuncSetAttribute(gemm_bf16p<1>,
                         cudaFuncAttributeMaxDynamicSharedMemorySize, gemm_smem);
    cudaFuncSetAttribute(flash_mma,
                         cudaFuncAttributeMaxDynamicSharedMemorySize, flash_smem);

    // 0. rope tables
    rope_tab<<<NTOK * 32 / 256, 256>>>(rc, rs);

    // 1. LayerNorm -> split bf16
    ln_kernel<<<NTOK, 256>>>(x, gamma, xn_hi, xn_lo);

    // 1b. all weight splits in one kernel
    wsplit_all<<<dim3(4 * DIM / 512, DIM), 256>>>(
        Wq, Wkv, Wo, wqkv_hi, wqkv_lo, wo_hi, wo_lo);

    // 2. qkv = xn @ [Wq | Wkv]; q,k plain fp32; v split in epilogue
    gemm_bf16p<1><<<dim3(QKV_LD / 128, NTOK / 128), 256, gemm_smem>>>(
        xn_hi, xn_lo, wqkv_hi, wqkv_lo, qkv, DIM, DIM, QKV_LD, QKV_LD,
        v_hi, v_lo);

    // 3a. q rope+split (table)
    rope_split_q<<<NTOK * 512 / 256, 256>>>(qkv, rc, rs, q_hi, q_lo);

    // 3b. bilinear K transform (RoPE via table) -> kt hi/lo [h][e][n]
    bilinear_kernel<<<dim3(NTOK / 64, NHEADS), 256>>>(
        k, QKV_LD, Wb, rc, rs, kt_hi, kt_lo);

    // 4. flash attention -> ao split bf16
    flash_mma<<<dim3(NTOK / 128, NHEADS), 256, flash_smem>>>(
        q_hi, q_lo, kt_hi, kt_lo, v_hi, v_lo, ao_hi, ao_lo);

    // 5. out = ao @ Wo
    gemm_bf16p<0><<<dim3(DIM / 128, NTOK / 128), 256, gemm_smem>>>(
        ao_hi, ao_lo, wo_hi, wo_lo, out, DIM, DIM, DIM, DIM,
        nullptr, nullptr);
}